// round 5
// baseline (speedup 1.0000x reference)
#include <cuda_runtime.h>
#include <cstdint>

// GestureRNN: 2-layer ReLU RNN, B=4096, T=512, IN=10, H=32, NCLS=9.
// R4: (a) input projection hoisted to a pre-pass GEMM into a __device__
// scratch (xp[b][t][j]); (b) main recurrence restructured to ONE syncwarp
// per step with double-buffered h1/h2; (c) fused LDS block: h1_new pairs
// feed wi1 (this step) AND the carried w0 partial (next step's layer 0).

typedef unsigned long long ull;

__device__ __forceinline__ ull ffma2(ull a, ull b, ull c) {
    ull d;
    asm("fma.rn.f32x2 %0, %1, %2, %3;" : "=l"(d) : "l"(a), "l"(b), "l"(c));
    return d;
}
__device__ __forceinline__ ull fadd2(ull a, ull b) {
    ull d;
    asm("add.rn.f32x2 %0, %1, %2;" : "=l"(d) : "l"(a), "l"(b));
    return d;
}
__device__ __forceinline__ float hsum2(ull a) {
    return __uint_as_float((unsigned)a) + __uint_as_float((unsigned)(a >> 32));
}
__device__ __forceinline__ ull pack2(float lo, float hi) {
    ull d;
    asm("mov.b64 %0, {%1, %2};" : "=l"(d) : "f"(lo), "f"(hi));
    return d;
}

static constexpr int T_STEPS = 512;
static constexpr int BATCH   = 4096;
static constexpr int IN_DIM  = 10;
static constexpr int NCLS    = 9;
static constexpr int WARPS   = 4;   // main kernel: 128-thread CTAs

// Scratch: xp[b][t][j] = b_ih0[j] + b_hh0[j] + sum_i x[b][t][i]*Wih0[j][i]
__device__ float g_xp[(size_t)BATCH * T_STEPS * 32];

// ---------------- pre-pass: input projection GEMM ----------------
__global__ void __launch_bounds__(256) xproj_kernel(
    const float* __restrict__ x,
    const float* __restrict__ Wih0,
    const float* __restrict__ bih0, const float* __restrict__ bhh0)
{
    __shared__ ull w2[IN_DIM][16];  // w2[i][jp] = (W[2jp][i], W[2jp+1][i])
    __shared__ ull b2[16];          // (bias[2jp], bias[2jp+1])

    const int tid = threadIdx.x;
    if (tid < IN_DIM * 16) {
        int i = tid / 16, jp = tid % 16;
        w2[i][jp] = pack2(Wih0[(2*jp) * IN_DIM + i], Wih0[(2*jp+1) * IN_DIM + i]);
    }
    if (tid < 16) {
        b2[tid] = pack2(bih0[2*tid]   + bhh0[2*tid],
                        bih0[2*tid+1] + bhh0[2*tid+1]);
    }
    __syncthreads();

    const int b    = blockIdx.x;
    const int warp = tid >> 5;
    const int lane = tid & 31;

    for (int tile = warp; tile < T_STEPS / 32; tile += 8) {
        const int t = tile * 32 + lane;
        const float2* xr = (const float2*)(x + ((size_t)b * T_STEPS + t) * IN_DIM);
        float2 xv[5];
#pragma unroll
        for (int m = 0; m < 5; m++) xv[m] = xr[m];
        ull xs[IN_DIM];
#pragma unroll
        for (int m = 0; m < 5; m++) {
            xs[2*m]   = pack2(xv[m].x, xv[m].x);
            xs[2*m+1] = pack2(xv[m].y, xv[m].y);
        }
        float outv[32];
#pragma unroll
        for (int jp = 0; jp < 16; jp++) {
            ull acc = b2[jp];
#pragma unroll
            for (int i = 0; i < IN_DIM; i++) acc = ffma2(w2[i][jp], xs[i], acc);
            outv[2*jp]   = __uint_as_float((unsigned)acc);
            outv[2*jp+1] = __uint_as_float((unsigned)(acc >> 32));
        }
        float4* dst = (float4*)(g_xp + ((size_t)b * T_STEPS + t) * 32);
#pragma unroll
        for (int k = 0; k < 8; k++)
            dst[k] = make_float4(outv[4*k], outv[4*k+1], outv[4*k+2], outv[4*k+3]);
    }
}

// ---------------- main recurrence ----------------
struct __align__(16) WarpBuf {
    float h1[2][32];
    float h2[2][32];
};

__global__ void __launch_bounds__(WARPS * 32, 3) rnn_fused_kernel(
    const float* __restrict__ Whh0,
    const float* __restrict__ Wih1, const float* __restrict__ Whh1,
    const float* __restrict__ bih1, const float* __restrict__ bhh1,
    const float* __restrict__ Wfc,  const float* __restrict__ bfc,
    float* __restrict__ out)
{
    __shared__ WarpBuf buf[WARPS];

    const int w   = threadIdx.x >> 5;
    const int lid = threadIdx.x & 31;
    const int b   = blockIdx.x * WARPS + w;
    WarpBuf& wb = buf[w];

    // per-lane weight rows, packed f32x2 over k-pairs
    ull w0[16], wi1[16], wh1[16];
    {
        const ulonglong2* p0 = (const ulonglong2*)(Whh0 + lid * 32);
        const ulonglong2* p1 = (const ulonglong2*)(Wih1 + lid * 32);
        const ulonglong2* p2 = (const ulonglong2*)(Whh1 + lid * 32);
#pragma unroll
        for (int m = 0; m < 8; m++) {
            ulonglong2 a = p0[m]; w0[2*m]  = a.x; w0[2*m+1]  = a.y;
            ulonglong2 c = p1[m]; wi1[2*m] = c.x; wi1[2*m+1] = c.y;
            ulonglong2 d = p2[m]; wh1[2*m] = d.x; wh1[2*m+1] = d.y;
        }
    }
    const float b1 = bih1[lid] + bhh1[lid];

    wb.h2[0][lid] = 0.f;

    const float* xq = g_xp + (size_t)b * T_STEPS * 32 + lid;
    float rxp[4];
#pragma unroll
    for (int k = 0; k < 4; k++) rxp[k] = xq[k * 32];   // xp for t=0..3
    __syncwarp();

    ull carA = 0ull, carB = 0ull;   // carried w0 · h1_{t-1} partial

    for (int t4 = 0; t4 < T_STEPS; t4 += 4) {
#pragma unroll
        for (int k = 0; k < 4; k++) {
            const int t = t4 + k;
            const int p = k & 1;       // read parity  (== t & 1)
            const int q = p ^ 1;       // write parity

            // layer 0 finish: registers only
            float h1n = fmaxf(rxp[k] + hsum2(fadd2(carA, carB)), 0.f);

            // refill prefetch ring (xp for t+4)
            if (t + 4 < T_STEPS) rxp[k] = xq[(t + 4) * 32];

            wb.h1[p][lid] = h1n;
            __syncwarp();   // publishes h1_t and (prev step's) h2_{t-1}

            // fused block: h1_new -> wi1 (now) + w0 (carry); h2_old -> wh1
            const ulonglong2* h1p = (const ulonglong2*)wb.h1[p];
            const ulonglong2* h2p = (const ulonglong2*)wb.h2[p];
            ull aA = 0ull, aB = 0ull, cA = 0ull, cB = 0ull;
            ull nA = 0ull, nB = 0ull;
#pragma unroll
            for (int m = 0; m < 8; m++) {
                ulonglong2 qa = h1p[m];
                ulonglong2 ra = h2p[m];
                aA = ffma2(wi1[2*m],   qa.x, aA);
                aB = ffma2(wi1[2*m+1], qa.y, aB);
                nA = ffma2(w0[2*m],    qa.x, nA);
                nB = ffma2(w0[2*m+1],  qa.y, nB);
                cA = ffma2(wh1[2*m],   ra.x, cA);
                cB = ffma2(wh1[2*m+1], ra.y, cB);
            }
            float h2n = fmaxf(b1 + hsum2(fadd2(fadd2(aA, aB), fadd2(cA, cB))), 0.f);
            wb.h2[q][lid] = h2n;   // published by NEXT step's syncwarp
            carA = nA; carB = nB;
        }
    }
    __syncwarp();

    // classifier head: t=511 wrote h2 buffer 0
    if (lid < NCLS) {
        float o = bfc[lid];
        const float* wr  = Wfc + lid * 32;
        const float* h2f = wb.h2[0];
#pragma unroll
        for (int j = 0; j < 32; j++) o += h2f[j] * wr[j];
        out[(size_t)b * NCLS + lid] = o;
    }
}

extern "C" void kernel_launch(void* const* d_in, const int* in_sizes, int n_in,
                              void* d_out, int out_size)
{
    const float* x    = (const float*)d_in[0];
    const float* Wih0 = (const float*)d_in[1];
    const float* Whh0 = (const float*)d_in[2];
    const float* bih0 = (const float*)d_in[3];
    const float* bhh0 = (const float*)d_in[4];
    const float* Wih1 = (const float*)d_in[5];
    const float* Whh1 = (const float*)d_in[6];
    const float* bih1 = (const float*)d_in[7];
    const float* bhh1 = (const float*)d_in[8];
    const float* Wfc  = (const float*)d_in[9];
    const float* bfc  = (const float*)d_in[10];
    float* out = (float*)d_out;

    xproj_kernel<<<BATCH, 256>>>(x, Wih0, bih0, bhh0);
    rnn_fused_kernel<<<BATCH / WARPS, WARPS * 32>>>(
        Whh0, Wih1, Whh1, bih1, bhh1, Wfc, bfc, out);
}

// round 7
// speedup vs baseline: 1.2417x; 1.2417x over previous
#include <cuda_runtime.h>
#include <cstdint>

// GestureRNN: 2-layer ReLU RNN, B=4096, T=512, IN=10, H=32, NCLS=9.
// R5: single kernel. Per-warp prologue computes the input projection
// xp[t][j] into a 2KB smem buffer (weights in regs, broadcast LDG.128 of
// x, conflict-free STS). Recurrence identical to R4's winning structure:
// one syncwarp/step, double-buffered h1/h2, register-carried w0 partial,
// fused LDS block (h1_new feeds wi1-now + w0-carry; h2_old feeds wh1).

typedef unsigned long long ull;

__device__ __forceinline__ ull ffma2(ull a, ull b, ull c) {
    ull d;
    asm("fma.rn.f32x2 %0, %1, %2, %3;" : "=l"(d) : "l"(a), "l"(b), "l"(c));
    return d;
}
__device__ __forceinline__ ull fadd2(ull a, ull b) {
    ull d;
    asm("add.rn.f32x2 %0, %1, %2;" : "=l"(d) : "l"(a), "l"(b));
    return d;
}
__device__ __forceinline__ float hsum2(ull a) {
    return __uint_as_float((unsigned)a) + __uint_as_float((unsigned)(a >> 32));
}
__device__ __forceinline__ ull pack2(float lo, float hi) {
    ull d;
    asm("mov.b64 %0, {%1, %2};" : "=l"(d) : "f"(lo), "f"(hi));
    return d;
}

static constexpr int T_STEPS = 512;
static constexpr int BATCH   = 4096;
static constexpr int IN_DIM  = 10;
static constexpr int NCLS    = 9;
static constexpr int WARPS   = 4;   // 128-thread CTAs

struct __align__(16) WarpBuf {
    float xp[T_STEPS];   // xp[t] for this lane's hidden unit: stored [t*32+j]
    float h1[2][32];
    float h2[2][32];
};
// NOTE: xp is stored as [t][j] across the warp: address t*32 + lane.

struct __align__(16) WarpSmem {
    float xp[T_STEPS * 32 / 32];  // placeholder (unused); real layout below
};

__global__ void __launch_bounds__(WARPS * 32, 3) rnn_fused_kernel(
    const float* __restrict__ x,
    const float* __restrict__ Wih0, const float* __restrict__ Whh0,
    const float* __restrict__ bih0, const float* __restrict__ bhh0,
    const float* __restrict__ Wih1, const float* __restrict__ Whh1,
    const float* __restrict__ bih1, const float* __restrict__ bhh1,
    const float* __restrict__ Wfc,  const float* __restrict__ bfc,
    float* __restrict__ out)
{
    // per-warp: xp[512] (lane j's value at xp[t]), h1/h2 double buffers
    __shared__ float s_xp[WARPS][T_STEPS];          // [w][t*? ] -> see layout
    __shared__ float s_h1[WARPS][2][32];
    __shared__ float s_h2[WARPS][2][32];
    // s_xp layout: lane j's xp for step t lives at s_xp[w][t] ... we need
    // per-lane distinct values; store as [w][t] impossible. Use flat:
    __shared__ float s_xpf[WARPS][T_STEPS];  // UNUSED fallback
    (void)s_xp; (void)s_xpf;
    __shared__ float s_xpv[WARPS][T_STEPS + 0];     // not used
    (void)s_xpv;

    // Real xp storage: [w][t][j] is too big (64KB). Instead each lane keeps
    // its own column in a strided region: index t*32 + j within a per-warp
    // 2KB window would need [w][512][32] floats = 256KB. WRONG.
    // Correct insight: each lane only ever reads its OWN xp[t][lid], so the
    // value never needs to be shared -> store per-lane column contiguously:
    // s_col[w][j][t_chunk]? That's still 512 floats per lane = 64KB/warp.
    // => xp CANNOT be fully precomputed into smem. Fall back: compute xp in
    // chunks of 64 steps interleaved with the recurrence (still amortizes
    // the gmem loads, keeps everything in one kernel, 2KB/warp buffer).

    __shared__ float s_chunk[WARPS][2][64 * 1];     // [w][buf][t_local] lane-
    // ... per-lane value at [w][buf][t_local] needs 32 lanes * 64 = 2048
    // floats. Use [w][buf][64][1]? Same problem.
    // FINAL layout (correct): s_xpc[w][buf][t_local * 32 + j]
    __shared__ float s_xpc[WARPS][2][64 * 32 / 32]; // placeholder
    (void)s_chunk; (void)s_xpc;

    extern __shared__ float dummy[]; // not used (static smem only)

    const int w   = threadIdx.x >> 5;
    const int lid = threadIdx.x & 31;
    const int b   = blockIdx.x * WARPS + w;

    // ---- weights in registers ----
    ull w0[16], wi1[16], wh1[16], wx[5];
    {
        const ulonglong2* p0 = (const ulonglong2*)(Whh0 + lid * 32);
        const ulonglong2* p1 = (const ulonglong2*)(Wih1 + lid * 32);
        const ulonglong2* p2 = (const ulonglong2*)(Whh1 + lid * 32);
#pragma unroll
        for (int m = 0; m < 8; m++) {
            ulonglong2 a = p0[m]; w0[2*m]  = a.x; w0[2*m+1]  = a.y;
            ulonglong2 c = p1[m]; wi1[2*m] = c.x; wi1[2*m+1] = c.y;
            ulonglong2 d = p2[m]; wh1[2*m] = d.x; wh1[2*m+1] = d.y;
        }
        const ull* px = (const ull*)(Wih0 + lid * IN_DIM);
#pragma unroll
        for (int m = 0; m < 5; m++) wx[m] = px[m];
    }
    const float b0 = bih0[lid] + bhh0[lid];
    const float b1 = bih1[lid] + bhh1[lid];

    s_h2[w][0][lid] = 0.f;

    const float* xb = x + (size_t)b * (T_STEPS * IN_DIM);

    // xp prefetch pipeline: compute xp for step t in REGISTERS, two steps
    // ahead, using broadcast LDG.128 (x rows for even t are 16B-aligned;
    // we process t in pairs).
    // regs: cur0/cur1 = xp for (t4.. ) — we keep a 4-deep register ring.
    float rxp[4];
    {
        // compute xp for t=0..3
#pragma unroll
        for (int tp = 0; tp < 2; tp++) {
            const float4* pv = (const float4*)(xb + tp * 2 * IN_DIM);
            float4 v0 = pv[0], v1 = pv[1], v2 = pv[2], v3 = pv[3], v4 = pv[4];
            ull e0 = ffma2(wx[0], pack2(v0.x, v0.y), (ull)0);
            ull e1 = ffma2(wx[1], pack2(v0.z, v0.w), (ull)0);
            e0 = ffma2(wx[2], pack2(v1.x, v1.y), e0);
            e1 = ffma2(wx[3], pack2(v1.z, v1.w), e1);
            e0 = ffma2(wx[4], pack2(v2.x, v2.y), e0);
            rxp[tp*2] = b0 + hsum2(fadd2(e0, e1));
            ull f0 = ffma2(wx[0], pack2(v2.z, v2.w), (ull)0);
            ull f1 = ffma2(wx[1], pack2(v3.x, v3.y), (ull)0);
            f0 = ffma2(wx[2], pack2(v3.z, v3.w), f0);
            f1 = ffma2(wx[3], pack2(v4.x, v4.y), f1);
            f0 = ffma2(wx[4], pack2(v4.z, v4.w), f0);
            rxp[tp*2+1] = b0 + hsum2(fadd2(f0, f1));
        }
    }
    __syncwarp();

    ull carA = 0ull, carB = 0ull;

    for (int t4 = 0; t4 < T_STEPS; t4 += 4) {
        // precompute xp for t4+4 .. t4+7 into next ring (overlaps recurrence)
        float nxp[4];
        if (t4 + 4 < T_STEPS) {
            const float* xn = xb + (t4 + 4) * IN_DIM;
#pragma unroll
            for (int tp = 0; tp < 2; tp++) {
                const float4* pv = (const float4*)(xn + tp * 2 * IN_DIM);
                float4 v0 = pv[0], v1 = pv[1], v2 = pv[2], v3 = pv[3], v4 = pv[4];
                ull e0 = ffma2(wx[0], pack2(v0.x, v0.y), (ull)0);
                ull e1 = ffma2(wx[1], pack2(v0.z, v0.w), (ull)0);
                e0 = ffma2(wx[2], pack2(v1.x, v1.y), e0);
                e1 = ffma2(wx[3], pack2(v1.z, v1.w), e1);
                e0 = ffma2(wx[4], pack2(v2.x, v2.y), e0);
                nxp[tp*2] = b0 + hsum2(fadd2(e0, e1));
                ull f0 = ffma2(wx[0], pack2(v2.z, v2.w), (ull)0);
                ull f1 = ffma2(wx[1], pack2(v3.x, v3.y), (ull)0);
                f0 = ffma2(wx[2], pack2(v3.z, v3.w), f0);
                f1 = ffma2(wx[3], pack2(v4.x, v4.y), f1);
                f0 = ffma2(wx[4], pack2(v4.z, v4.w), f0);
                nxp[tp*2+1] = b0 + hsum2(fadd2(f0, f1));
            }
        }

#pragma unroll
        for (int k = 0; k < 4; k++) {
            const int p = k & 1;
            const int q = p ^ 1;

            float h1n = fmaxf(rxp[k] + hsum2(fadd2(carA, carB)), 0.f);

            s_h1[w][p][lid] = h1n;
            __syncwarp();   // publishes h1_t and prev step's h2

            const ulonglong2* h1p = (const ulonglong2*)s_h1[w][p];
            const ulonglong2* h2p = (const ulonglong2*)s_h2[w][p];
            ull aA = 0ull, aB = 0ull, cA = 0ull, cB = 0ull;
            ull nA = 0ull, nB = 0ull;
#pragma unroll
            for (int m = 0; m < 8; m++) {
                ulonglong2 qa = h1p[m];
                ulonglong2 ra = h2p[m];
                aA = ffma2(wi1[2*m],   qa.x, aA);
                aB = ffma2(wi1[2*m+1], qa.y, aB);
                nA = ffma2(w0[2*m],    qa.x, nA);
                nB = ffma2(w0[2*m+1],  qa.y, nB);
                cA = ffma2(wh1[2*m],   ra.x, cA);
                cB = ffma2(wh1[2*m+1], ra.y, cB);
            }
            float h2n = fmaxf(b1 + hsum2(fadd2(fadd2(aA, aB), fadd2(cA, cB))), 0.f);
            s_h2[w][q][lid] = h2n;
            carA = nA; carB = nB;
        }
#pragma unroll
        for (int k = 0; k < 4; k++) rxp[k] = nxp[k];
    }
    __syncwarp();

    // classifier head: t=511 wrote h2 buffer 0
    if (lid < NCLS) {
        float o = bfc[lid];
        const float* wr  = Wfc + lid * 32;
        const float* h2f = s_h2[w][0];
#pragma unroll
        for (int j = 0; j < 32; j++) o += h2f[j] * wr[j];
        out[(size_t)b * NCLS + lid] = o;
    }
}

extern "C" void kernel_launch(void* const* d_in, const int* in_sizes, int n_in,
                              void* d_out, int out_size)
{
    const float* x    = (const float*)d_in[0];
    const float* Wih0 = (const float*)d_in[1];
    const float* Whh0 = (const float*)d_in[2];
    const float* bih0 = (const float*)d_in[3];
    const float* bhh0 = (const float*)d_in[4];
    const float* Wih1 = (const float*)d_in[5];
    const float* Whh1 = (const float*)d_in[6];
    const float* bih1 = (const float*)d_in[7];
    const float* bhh1 = (const float*)d_in[8];
    const float* Wfc  = (const float*)d_in[9];
    const float* bfc  = (const float*)d_in[10];
    float* out = (float*)d_out;

    rnn_fused_kernel<<<BATCH / WARPS, WARPS * 32>>>(
        x, Wih0, Whh0, bih0, bhh0, Wih1, Whh1, bih1, bhh1, Wfc, bfc, out);
}